// round 2
// baseline (speedup 1.0000x reference)
#include <cuda_runtime.h>
#include <math.h>

#define UNUM 500000
#define B_ 4096
#define F_ 64
#define D_ 256
#define M_ 32
#define KTS 260   // padded Key^T row stride (floats): 260*4=1040B -> conflict-free float4 reads

// ---- scratch (device globals; no allocation allowed) ----
__device__ float g_uid [B_*D_];                 // raw uid rows
__device__ float g_uidn[B_*D_];                 // l2-normalized uid rows
__device__ float g_colsum[F_*M_];               // softmax-over-batch denominators
__device__ float g_eatt[(size_t)B_*F_*M_];      // exp(att_key)  (32 MB)
__device__ float g_f2  [(size_t)B_*F_*D_];      // f2 tensor     (256 MB)

__device__ __forceinline__ float wred32(float v){
#pragma unroll
    for (int o = 16; o; o >>= 1) v += __shfl_xor_sync(0xffffffffu, v, o);
    return v;
}

// ------------------------------------------------------------------
// K0: uid gather + l2 norm, zero colsum
// ------------------------------------------------------------------
__global__ void __launch_bounds__(256) k0_prep(const int* __restrict__ input_u,
                                               const float* __restrict__ uidW){
    int b = blockIdx.x, t = threadIdx.x;
    int u = input_u[b];
    float v = uidW[(size_t)u * D_ + t];
    __shared__ float red[8];
    __shared__ float invs;
    float s = wred32(v * v);
    if ((t & 31) == 0) red[t >> 5] = s;
    __syncthreads();
    if (t == 0){
        float x = 0.f;
#pragma unroll
        for (int i = 0; i < 8; i++) x += red[i];
        invs = 1.f / fmaxf(sqrtf(x), 1e-12f);
    }
    __syncthreads();
    g_uid [b * D_ + t] = v;
    g_uidn[b * D_ + t] = v * invs;
    if (b < 8) g_colsum[b * 256 + t] = 0.f;    // 8*256 == F_*M_ == 2048
}

// ------------------------------------------------------------------
// K1: per (b,f): fe gather -> cross -> att_key -> exp ; store g_eatt;
//     block-combined atomic into g_colsum. Block = 64 rows (same f).
// ------------------------------------------------------------------
__global__ void __launch_bounds__(256,2) k1_att(const int* __restrict__ input_uf,
                                                const float* __restrict__ uidW,
                                                const float* __restrict__ Key){
    extern __shared__ float sm[];
    float* Kt  = sm;                 // [32][260] Key transposed, padded
    float* crs = Kt + M_ * KTS;      // [64][256] cross rows
    float* eat = crs + 64 * D_;      // [64][32]
    int t = threadIdx.x;
    int f = blockIdx.y;
    int bbase = blockIdx.x * 64;
    int w = t >> 5, l = t & 31;

    for (int i = t; i < D_ * M_; i += 256){     // Key is [D][M] row-major
        int d = i >> 5, m = i & 31;
        Kt[m * KTS + d] = Key[i];
    }

    // phase A: each warp builds 8 cross rows
#pragma unroll 1
    for (int rr = 0; rr < 8; ++rr){
        int r = w * 8 + rr;
        int b = bbase + r;
        int uf = input_uf[b * F_ + f];
        float msk = (uf != UNUM) ? 1.f : 0.f;
        const float4* fp = (const float4*)(uidW + (size_t)uf * D_);
        float4 a0 = fp[l], a1 = fp[32 + l];
        a0.x *= msk; a0.y *= msk; a0.z *= msk; a0.w *= msk;
        a1.x *= msk; a1.y *= msk; a1.z *= msk; a1.w *= msk;
        float ss = a0.x*a0.x + a0.y*a0.y + a0.z*a0.z + a0.w*a0.w
                 + a1.x*a1.x + a1.y*a1.y + a1.z*a1.z + a1.w*a1.w;
        ss = wred32(ss);
        float inv = 1.f / fmaxf(sqrtf(ss), 1e-12f);
        const float4* up = (const float4*)(g_uidn + (size_t)b * D_);
        float4 u0 = up[l], u1 = up[32 + l];
        float4 c0, c1;
        c0.x = a0.x*inv*u0.x; c0.y = a0.y*inv*u0.y; c0.z = a0.z*inv*u0.z; c0.w = a0.w*inv*u0.w;
        c1.x = a1.x*inv*u1.x; c1.y = a1.y*inv*u1.y; c1.z = a1.z*inv*u1.z; c1.w = a1.w*inv*u1.w;
        ((float4*)(crs + r * D_))[l]      = c0;
        ((float4*)(crs + r * D_))[32 + l] = c1;
    }
    __syncthreads();

    // phase B: thread (w,l): rows w*8..w*8+7, memory slot m=l
    float acc[8];
#pragma unroll
    for (int i = 0; i < 8; i++) acc[i] = 0.f;
    const float* kt = Kt + l * KTS;
#pragma unroll 4
    for (int d = 0; d < D_; d += 4){
        float4 kv = *(const float4*)(kt + d);
#pragma unroll
        for (int i = 0; i < 8; i++){
            float4 c = *(const float4*)(crs + (w * 8 + i) * D_ + d);
            acc[i] += c.x*kv.x + c.y*kv.y + c.z*kv.z + c.w*kv.w;
        }
    }
#pragma unroll
    for (int i = 0; i < 8; i++) eat[(w * 8 + i) * M_ + l] = expf(acc[i]);
    __syncthreads();

    for (int i = t; i < 64 * M_; i += 256){
        int r = i >> 5, m = i & 31;
        g_eatt[((size_t)(bbase + r) * F_ + f) * M_ + m] = eat[i];
    }
    if (t < M_){
        float s = 0.f;
#pragma unroll 8
        for (int r = 0; r < 64; r++) s += eat[r * M_ + t];
        atomicAdd(&g_colsum[f * M_ + t], s);
    }
}

// ------------------------------------------------------------------
// K2a: per (b,f): att_mem = mask*eatt/colsum ; f1 = att_mem@Mem ; f2 = f1*fe
// ------------------------------------------------------------------
__global__ void __launch_bounds__(256,2) k2a_f2(const int* __restrict__ input_uf,
                                                const float* __restrict__ uidW,
                                                const float* __restrict__ MemW){
    extern __shared__ float sm[];
    float* fes  = sm;                 // [64][256] masked fe rows
    float* attm = fes + 64 * D_;      // [64][32]
    float* Ms   = attm + 64 * M_;     // [32][256]
    float* cs   = Ms + M_ * D_;       // [32] 1/colsum
    float* vm   = cs + M_;            // [64]
    int t = threadIdx.x, w = t >> 5, l = t & 31;
    int f = blockIdx.y, bbase = blockIdx.x * 64;

    for (int i = t; i < M_ * D_; i += 256) Ms[i] = MemW[i];
    if (t < M_) cs[t] = 1.f / g_colsum[f * M_ + t];

#pragma unroll 1
    for (int rr = 0; rr < 8; ++rr){
        int r = w * 8 + rr, b = bbase + r;
        int uf = input_uf[b * F_ + f];
        float msk = (uf != UNUM) ? 1.f : 0.f;
        const float4* fp = (const float4*)(uidW + (size_t)uf * D_);
        float4 a0 = fp[l], a1 = fp[32 + l];
        a0.x *= msk; a0.y *= msk; a0.z *= msk; a0.w *= msk;
        a1.x *= msk; a1.y *= msk; a1.z *= msk; a1.w *= msk;
        ((float4*)(fes + r * D_))[l]      = a0;
        ((float4*)(fes + r * D_))[32 + l] = a1;
        if (l == 0) vm[r] = msk;
    }
    __syncthreads();

    for (int i = t; i < 64 * M_; i += 256){
        int r = i >> 5, m = i & 31;
        attm[i] = vm[r] * g_eatt[((size_t)(bbase + r) * F_ + f) * M_ + m] * cs[m];
    }
    __syncthreads();

    // phase B: thread (w,l): rows w*8..+7, cols d = l*8..l*8+7
    float f1r[8][8];
#pragma unroll
    for (int i = 0; i < 8; i++)
#pragma unroll
        for (int j = 0; j < 8; j++) f1r[i][j] = 0.f;
    const float4* Ms4 = (const float4*)Ms;
#pragma unroll 1
    for (int m = 0; m < M_; m++){
        float4 m0 = Ms4[m * 64 + l * 2];
        float4 m1 = Ms4[m * 64 + l * 2 + 1];
#pragma unroll
        for (int i = 0; i < 8; i++){
            float a = attm[(w * 8 + i) * M_ + m];
            f1r[i][0] += a * m0.x; f1r[i][1] += a * m0.y;
            f1r[i][2] += a * m0.z; f1r[i][3] += a * m0.w;
            f1r[i][4] += a * m1.x; f1r[i][5] += a * m1.y;
            f1r[i][6] += a * m1.z; f1r[i][7] += a * m1.w;
        }
    }
#pragma unroll
    for (int i = 0; i < 8; i++){
        int r = w * 8 + i;
        const float4* fr = (const float4*)(fes + r * D_);
        float4 e0 = fr[l * 2], e1 = fr[l * 2 + 1];
        float4 o0, o1;
        o0.x = f1r[i][0] * e0.x; o0.y = f1r[i][1] * e0.y;
        o0.z = f1r[i][2] * e0.z; o0.w = f1r[i][3] * e0.w;
        o1.x = f1r[i][4] * e1.x; o1.y = f1r[i][5] * e1.y;
        o1.z = f1r[i][6] * e1.z; o1.w = f1r[i][7] * e1.w;
        float4* dst = (float4*)(g_f2 + ((size_t)(bbase + r) * F_ + f) * D_);
        dst[l * 2]     = o0;
        dst[l * 2 + 1] = o1;
    }
}

// ------------------------------------------------------------------
// K2b: [128 x 256] @ WA[256 x 256] tile GEMM (rows = 2 b x 64 f) + full
//      fused epilogue: relu, j=exp(h.u), friend agg, user, att1, score.
// ------------------------------------------------------------------
__global__ void __launch_bounds__(512,1) k2b_gemm(
        const float* __restrict__ WA, const float* __restrict__ BA,
        const float* __restrict__ Uom, const float* __restrict__ E,
        const int* __restrict__ input_uf, const int* __restrict__ input_i,
        const float* __restrict__ iidW, const float* __restrict__ i_bias,
        float* __restrict__ out){
    extern __shared__ float sm[];
    float* Asm = sm;                  // [128][32]
    float* Bsm = Asm + 128 * 32;      // [32][256]
    __shared__ float jsm[128];
    __shared__ float sj[2];
    __shared__ float r0s[16], r1s[16];
    __shared__ float a0s[2], a1s[2];

    int t = threadIdx.x;
    int p = blockIdx.x;
    int tr = t >> 5, tc = t & 31;
    size_t arow0 = (size_t)p * 128;

    float acc[8][8];
#pragma unroll
    for (int i = 0; i < 8; i++)
#pragma unroll
        for (int j = 0; j < 8; j++) acc[i][j] = 0.f;

    const float4* A4g = (const float4*)g_f2;
    const float4* B4g = (const float4*)WA;
    float4* Asm4w = (float4*)Asm;
    float4* Bsm4w = (float4*)Bsm;

    for (int kt = 0; kt < 8; ++kt){
#pragma unroll
        for (int it = 0; it < 2; ++it){
            int q = t + it * 512;                    // 0..1023
            int r = q >> 3, c4 = q & 7;
            Asm4w[r * 8 + c4] = A4g[(arow0 + r) * 64 + kt * 8 + c4];
        }
#pragma unroll
        for (int it = 0; it < 4; ++it){
            int q = t + it * 512;                    // 0..2047
            int r = q >> 6, c4 = q & 63;
            Bsm4w[r * 64 + c4] = B4g[(size_t)(kt * 32 + r) * 64 + c4];
        }
        __syncthreads();
        const float4* Bsm4 = (const float4*)Bsm;
#pragma unroll 4
        for (int k = 0; k < 32; k++){
            float a[8];
#pragma unroll
            for (int i = 0; i < 8; i++) a[i] = Asm[(tr * 8 + i) * 32 + k];
            float4 b0 = Bsm4[k * 64 + tc * 2];
            float4 b1 = Bsm4[k * 64 + tc * 2 + 1];
            float bj[8] = {b0.x,b0.y,b0.z,b0.w,b1.x,b1.y,b1.z,b1.w};
#pragma unroll
            for (int i = 0; i < 8; i++)
#pragma unroll
                for (int j = 0; j < 8; j++) acc[i][j] += a[i] * bj[j];
        }
        __syncthreads();
    }

    // ---- epilogue ----
    int col0 = tc * 8;
    float ba_r[8], uo_r[8];
#pragma unroll
    for (int j = 0; j < 8; j++){ ba_r[j] = BA[col0 + j]; uo_r[j] = Uom[col0 + j]; }
#pragma unroll
    for (int i = 0; i < 8; i++){
        float s = 0.f;
#pragma unroll
        for (int j = 0; j < 8; j++){
            float h = fmaxf(acc[i][j] + ba_r[j], 0.f);
            s += h * uo_r[j];
        }
        s = wred32(s);
        if (tc == 0) jsm[tr * 8 + i] = s;
    }
    __syncthreads();

    int b0 = p * 2;
    if (t < 128){
        int b = b0 + (t >> 6), f = t & 63;
        float msk = (input_uf[b * F_ + f] != UNUM) ? 1.f : 0.f;
        jsm[t] = msk * expf(jsm[t]);
    }
    __syncthreads();
    if (t < 2){
        float s = 0.f;
        for (int q = 0; q < 64; q++) s += jsm[t * 64 + q];
        sj[t] = 1.f / (s + 1e-8f);
    }
    __syncthreads();

    // 512 threads = 2 b x 256 d
    int bb = t >> 8, d = t & 255;
    int b = b0 + bb;
    float fr = 0.f, fr2 = 0.f;
    const float* fbase = g_f2 + ((size_t)b * F_) * D_ + d;
#pragma unroll 4
    for (int f = 0; f < F_; f += 2){
        fr  += jsm[bb * 64 + f]     * fbase[(size_t)f * D_];
        fr2 += jsm[bb * 64 + f + 1] * fbase[(size_t)(f + 1) * D_];
    }
    fr = (fr + fr2) * sj[bb];
    float uidv = g_uid[b * D_ + d];
    float user = uidv + fr;
    float p0 = uidv * E[d * 2]     + user * E[(256 + d) * 2];
    float p1 = uidv * E[d * 2 + 1] + user * E[(256 + d) * 2 + 1];
    p0 = wred32(p0); p1 = wred32(p1);
    int wid = t >> 5;
    if ((t & 31) == 0){ r0s[wid] = p0; r1s[wid] = p1; }
    __syncthreads();
    if (t < 2){
        float L0 = 0.f, L1 = 0.f;
        for (int q = 0; q < 8; q++){ L0 += r0s[t * 8 + q]; L1 += r1s[t * 8 + q]; }
        float mx = fmaxf(L0, L1);
        float e0 = expf(L0 - mx), e1 = expf(L1 - mx);
        float inv = 1.f / (e0 + e1);
        a0s[t] = e0 * inv; a1s[t] = e1 * inv;
    }
    __syncthreads();
    float ufv = uidv * a0s[bb] + user * a1s[bb];
    int ii = input_i[b];
    float sc = ufv * iidW[(size_t)ii * D_ + d];
    sc = wred32(sc);
    if ((t & 31) == 0) r0s[wid] = sc;
    __syncthreads();
    if (t < 2){
        float s = 0.f;
        for (int q = 0; q < 8; q++) s += r0s[t * 8 + q];
        int bi = input_i[b0 + t];
        out[b0 + t] = s + i_bias[bi];
    }
}

// ------------------------------------------------------------------
extern "C" void kernel_launch(void* const* d_in, const int* in_sizes, int n_in,
                              void* d_out, int out_size){
    const int*   input_u  = (const int*)  d_in[0];
    const int*   input_i  = (const int*)  d_in[1];
    const int*   input_uf = (const int*)  d_in[2];
    const float* uidW     = (const float*)d_in[3];
    const float* iidW     = (const float*)d_in[4];
    const float* i_bias   = (const float*)d_in[5];
    const float* Key      = (const float*)d_in[6];
    const float* MemW     = (const float*)d_in[7];
    const float* WA       = (const float*)d_in[8];
    const float* BA       = (const float*)d_in[9];
    const float* Uom      = (const float*)d_in[10];
    const float* E        = (const float*)d_in[11];
    float* out = (float*)d_out;

    size_t sm1 = (size_t)(M_ * KTS + 64 * D_ + 64 * M_) * sizeof(float);          // ~104.5 KB
    size_t sm2 = (size_t)(64 * D_ + 64 * M_ + M_ * D_ + M_ + 64) * sizeof(float); // ~104.4 KB
    size_t sm3 = (size_t)(128 * 32 + 32 * 256) * sizeof(float);                   // 48 KB

    cudaFuncSetAttribute(k1_att,   cudaFuncAttributeMaxDynamicSharedMemorySize, (int)sm1);
    cudaFuncSetAttribute(k2a_f2,   cudaFuncAttributeMaxDynamicSharedMemorySize, (int)sm2);
    cudaFuncSetAttribute(k2b_gemm, cudaFuncAttributeMaxDynamicSharedMemorySize, (int)sm3);

    k0_prep<<<B_, 256>>>(input_u, uidW);
    k1_att <<<dim3(B_/64, F_), 256, sm1>>>(input_uf, uidW, Key);
    k2a_f2 <<<dim3(B_/64, F_), 256, sm2>>>(input_uf, uidW, MemW);
    k2b_gemm<<<B_/2, 512, sm3>>>(WA, BA, Uom, E, input_uf, input_i, iidW, i_bias, out);
}

// round 3
// speedup vs baseline: 2.4839x; 2.4839x over previous
#include <cuda_runtime.h>
#include <cuda_bf16.h>
#include <math.h>

#define UNUM 500000
#define B_ 4096
#define F_ 64
#define D_ 256
#define M_ 32
#define KTS 260

// ---- scratch ----
__device__ float g_uid [B_*D_];
__device__ float g_uidn[B_*D_];
__device__ float g_colsum[F_*M_];
__device__ float g_eatt[(size_t)B_*F_*M_];           // exp(att_key) 32 MB
__device__ __nv_bfloat16 g_fe[(size_t)B_*F_*D_];     // masked fe bf16, 128 MB

__device__ __forceinline__ float wred32(float v){
#pragma unroll
    for (int o = 16; o; o >>= 1) v += __shfl_xor_sync(0xffffffffu, v, o);
    return v;
}
__device__ __forceinline__ unsigned s2u(const void* p){
    return (unsigned)__cvta_generic_to_shared(p);
}
__device__ __forceinline__ unsigned bits2(__nv_bfloat162 v){
    return *(unsigned*)&v;
}

#define LDSM4(R, addr) asm volatile( \
    "ldmatrix.sync.aligned.m8n8.x4.shared.b16 {%0,%1,%2,%3}, [%4];" \
    : "=r"((R)[0]),"=r"((R)[1]),"=r"((R)[2]),"=r"((R)[3]) : "r"(addr))
#define LDSM4T(R, addr) asm volatile( \
    "ldmatrix.sync.aligned.m8n8.x4.trans.shared.b16 {%0,%1,%2,%3}, [%4];" \
    : "=r"((R)[0]),"=r"((R)[1]),"=r"((R)[2]),"=r"((R)[3]) : "r"(addr))
#define MMA16816(D, A, B0, B1) asm volatile( \
    "mma.sync.aligned.m16n8k16.row.col.f32.bf16.bf16.f32 " \
    "{%0,%1,%2,%3}, {%4,%5,%6,%7}, {%8,%9}, {%0,%1,%2,%3};" \
    : "+f"((D)[0]),"+f"((D)[1]),"+f"((D)[2]),"+f"((D)[3]) \
    : "r"((A)[0]),"r"((A)[1]),"r"((A)[2]),"r"((A)[3]),"r"(B0),"r"(B1))

// ------------------------------------------------------------------
// K0: uid gather + l2 norm, zero colsum
// ------------------------------------------------------------------
__global__ void __launch_bounds__(256) k0_prep(const int* __restrict__ input_u,
                                               const float* __restrict__ uidW){
    int b = blockIdx.x, t = threadIdx.x;
    int u = input_u[b];
    float v = uidW[(size_t)u * D_ + t];
    __shared__ float red[8];
    __shared__ float invs;
    float s = wred32(v * v);
    if ((t & 31) == 0) red[t >> 5] = s;
    __syncthreads();
    if (t == 0){
        float x = 0.f;
#pragma unroll
        for (int i = 0; i < 8; i++) x += red[i];
        invs = 1.f / fmaxf(sqrtf(x), 1e-12f);
    }
    __syncthreads();
    g_uid [b * D_ + t] = v;
    g_uidn[b * D_ + t] = v * invs;
    if (b < 8) g_colsum[b * 256 + t] = 0.f;
}

// ------------------------------------------------------------------
// K1: fe gather -> masked fe (store bf16) -> cross -> att_key -> exp
// ------------------------------------------------------------------
__global__ void __launch_bounds__(256,2) k1_att(const int* __restrict__ input_uf,
                                                const float* __restrict__ uidW,
                                                const float* __restrict__ Key){
    extern __shared__ float sm[];
    float* Kt  = sm;
    float* crs = Kt + M_ * KTS;
    float* eat = crs + 64 * D_;
    int t = threadIdx.x;
    int f = blockIdx.y;
    int bbase = blockIdx.x * 64;
    int w = t >> 5, l = t & 31;

    for (int i = t; i < D_ * M_; i += 256){
        int d = i >> 5, m = i & 31;
        Kt[m * KTS + d] = Key[i];
    }

#pragma unroll 1
    for (int rr = 0; rr < 8; ++rr){
        int r = w * 8 + rr;
        int b = bbase + r;
        int uf = input_uf[b * F_ + f];
        float msk = (uf != UNUM) ? 1.f : 0.f;
        const float4* fp = (const float4*)(uidW + (size_t)uf * D_);
        float4 a0 = fp[l], a1 = fp[32 + l];
        a0.x *= msk; a0.y *= msk; a0.z *= msk; a0.w *= msk;
        a1.x *= msk; a1.y *= msk; a1.z *= msk; a1.w *= msk;
        // store masked fe bf16
        {
            uint2 u0, u1;
            u0.x = bits2(__floats2bfloat162_rn(a0.x, a0.y));
            u0.y = bits2(__floats2bfloat162_rn(a0.z, a0.w));
            u1.x = bits2(__floats2bfloat162_rn(a1.x, a1.y));
            u1.y = bits2(__floats2bfloat162_rn(a1.z, a1.w));
            size_t rowg = ((size_t)b * F_ + f) * D_;
            *(uint2*)(g_fe + rowg + l * 4)       = u0;
            *(uint2*)(g_fe + rowg + 128 + l * 4) = u1;
        }
        float ss = a0.x*a0.x + a0.y*a0.y + a0.z*a0.z + a0.w*a0.w
                 + a1.x*a1.x + a1.y*a1.y + a1.z*a1.z + a1.w*a1.w;
        ss = wred32(ss);
        float inv = 1.f / fmaxf(sqrtf(ss), 1e-12f);
        const float4* up = (const float4*)(g_uidn + (size_t)b * D_);
        float4 u0 = up[l], u1 = up[32 + l];
        float4 c0, c1;
        c0.x = a0.x*inv*u0.x; c0.y = a0.y*inv*u0.y; c0.z = a0.z*inv*u0.z; c0.w = a0.w*inv*u0.w;
        c1.x = a1.x*inv*u1.x; c1.y = a1.y*inv*u1.y; c1.z = a1.z*inv*u1.z; c1.w = a1.w*inv*u1.w;
        ((float4*)(crs + r * D_))[l]      = c0;
        ((float4*)(crs + r * D_))[32 + l] = c1;
    }
    __syncthreads();

    float acc[8];
#pragma unroll
    for (int i = 0; i < 8; i++) acc[i] = 0.f;
    const float* kt = Kt + l * KTS;
#pragma unroll 4
    for (int d = 0; d < D_; d += 4){
        float4 kv = *(const float4*)(kt + d);
#pragma unroll
        for (int i = 0; i < 8; i++){
            float4 c = *(const float4*)(crs + (w * 8 + i) * D_ + d);
            acc[i] += c.x*kv.x + c.y*kv.y + c.z*kv.z + c.w*kv.w;
        }
    }
#pragma unroll
    for (int i = 0; i < 8; i++) eat[(w * 8 + i) * M_ + l] = expf(acc[i]);
    __syncthreads();

    for (int i = t; i < 64 * M_; i += 256){
        int r = i >> 5, m = i & 31;
        g_eatt[((size_t)(bbase + r) * F_ + f) * M_ + m] = eat[i];
    }
    if (t < M_){
        float s = 0.f;
#pragma unroll 8
        for (int r = 0; r < 64; r++) s += eat[r * M_ + t];
        atomicAdd(&g_colsum[f * M_ + t], s);
    }
}

// ------------------------------------------------------------------
// K2 fused: per 2 batches (128 rows): attmem -> f1 (MMA) -> f2 (smem)
//           -> h = f2@WA (MMA, streamed WA) -> j -> friend -> score
// ------------------------------------------------------------------
#define SA_S  264     // sA row stride (bf16)
#define SAT_S 40      // sAtt row stride (bf16)
#define OFF_SA   0
#define OFF_SW   67584
#define OFF_SMEM 101376
#define OFF_SATT 118272
#define OFF_SCS  128512
#define OFF_SBA  136704
#define OFF_SU   137728
#define OFF_JSM  138752
#define OFF_RED  139264
#define SMEM_K2  139520

__global__ void __launch_bounds__(256,1) k2_fused(
        const int* __restrict__ input_uf, const int* __restrict__ input_i,
        const float* __restrict__ iidW, const float* __restrict__ i_bias,
        const float* __restrict__ WA, const float* __restrict__ BA,
        const float* __restrict__ Uom, const float* __restrict__ E,
        const float* __restrict__ MemW, float* __restrict__ out){
    extern __shared__ char smraw[];
    __nv_bfloat16* sA   = (__nv_bfloat16*)(smraw + OFF_SA);    // [128][264] fe -> f2
    __nv_bfloat16* sW   = (__nv_bfloat16*)(smraw + OFF_SW);    // 2 x [32][264] WA chunks
    __nv_bfloat16* sMm  = (__nv_bfloat16*)(smraw + OFF_SMEM);  // [32][264] Mem bf16
    __nv_bfloat16* sAtt = (__nv_bfloat16*)(smraw + OFF_SATT);  // [128][40] attmem bf16
    float* scs  = (float*)(smraw + OFF_SCS);                   // [2048] 1/colsum
    float* sBA  = (float*)(smraw + OFF_SBA);                   // [256]
    float* sU   = (float*)(smraw + OFF_SU);                    // [256]
    float* jsm  = (float*)(smraw + OFF_JSM);                   // [128]
    float* rred = (float*)(smraw + OFF_RED);                   // [16]
    float* sjv  = rred + 16;                                   // [2]
    float* satt1= sjv + 2;                                     // [2]

    int t = threadIdx.x, p = blockIdx.x;
    int w = t >> 5, l = t & 31;
    size_t row0 = (size_t)p * 128;

    // ---- phase 1: loads ----
    {
        const uint4* src = (const uint4*)(g_fe + row0 * D_);
#pragma unroll
        for (int i = 0; i < 16; i++){
            int q = t + i * 256; int r = q >> 5, c = q & 31;
            *(uint4*)(sA + r * SA_S + c * 8) = src[r * 32 + c];
        }
    }
    {
        const float4* mf = (const float4*)MemW;
#pragma unroll
        for (int i = 0; i < 8; i++){
            int q = t + i * 256; int r = q >> 6, c = q & 63;
            float4 v = mf[q];
            uint2 u;
            u.x = bits2(__floats2bfloat162_rn(v.x, v.y));
            u.y = bits2(__floats2bfloat162_rn(v.z, v.w));
            *(uint2*)(sMm + r * SA_S + c * 4) = u;
        }
    }
#pragma unroll
    for (int i = t; i < 2048; i += 256) scs[i] = 1.f / g_colsum[i];
    sBA[t] = BA[t];
    sU[t]  = Uom[t];
    if (t < 128) jsm[t] = 0.f;
    __syncthreads();
    {
#pragma unroll
        for (int i = 0; i < 16; i++){
            int q = t + i * 256; int r = q >> 5, m = q & 31;
            float v = g_eatt[(row0 + r) * M_ + m] * scs[(r & 63) * 32 + m];
            sAtt[r * SAT_S + m] = __float2bfloat16(v);
        }
    }
    __syncthreads();

    int mw = w & 3, nw = w >> 2;
    int m0 = mw * 32, n0 = nw * 128;
    unsigned sA_b   = s2u(sA);
    unsigned sMm_b  = s2u(sMm);
    unsigned sAtt_b = s2u(sAtt);
    unsigned sW_b   = s2u(sW);

    // ---- GEMM1: f1 = attmem @ Mem, fold f2 = f1*fe into sA ----
    {
        unsigned aF[2][2][4];
#pragma unroll
        for (int mt = 0; mt < 2; mt++)
#pragma unroll
            for (int ks = 0; ks < 2; ks++){
                int row = m0 + mt * 16 + (l & 15);
                int col = ks * 16 + (l >> 4) * 8;
                LDSM4(aF[mt][ks], sAtt_b + 2 * (row * SAT_S + col));
            }
#pragma unroll
        for (int nt2 = 0; nt2 < 8; nt2++){
            float acc[2][2][4];
#pragma unroll
            for (int a = 0; a < 2; a++)
#pragma unroll
                for (int bq = 0; bq < 2; bq++)
#pragma unroll
                    for (int c = 0; c < 4; c++) acc[a][bq][c] = 0.f;
#pragma unroll
            for (int ks = 0; ks < 2; ks++){
                unsigned bfr[4];
                LDSM4T(bfr, sMm_b + 2 * ((ks * 16 + (l & 15)) * SA_S + n0 + nt2 * 16 + (l >> 4) * 8));
#pragma unroll
                for (int mt = 0; mt < 2; mt++){
                    MMA16816(acc[mt][0], aF[mt][ks], bfr[0], bfr[1]);
                    MMA16816(acc[mt][1], aF[mt][ks], bfr[2], bfr[3]);
                }
            }
#pragma unroll
            for (int mt = 0; mt < 2; mt++)
#pragma unroll
                for (int ntl = 0; ntl < 2; ntl++){
                    int r1 = m0 + mt * 16 + (l >> 2);
                    int c  = n0 + (nt2 * 2 + ntl) * 8 + 2 * (l & 3);
                    __nv_bfloat162* p0 = (__nv_bfloat162*)(sA + r1 * SA_S + c);
                    float2 fe0 = __bfloat1622float2(*p0);
                    *p0 = __floats2bfloat162_rn(acc[mt][ntl][0] * fe0.x,
                                                acc[mt][ntl][1] * fe0.y);
                    __nv_bfloat162* p1 = (__nv_bfloat162*)(sA + (r1 + 8) * SA_S + c);
                    float2 fe1 = __bfloat1622float2(*p1);
                    *p1 = __floats2bfloat162_rn(acc[mt][ntl][2] * fe1.x,
                                                acc[mt][ntl][3] * fe1.y);
                }
        }
    }
    __syncthreads();

    // ---- GEMM2: h = f2 @ WA (streamed bf16 WA), fold j epilogue ----
    float acc[2][16][4];
#pragma unroll
    for (int a = 0; a < 2; a++)
#pragma unroll
        for (int b = 0; b < 16; b++)
#pragma unroll
            for (int c = 0; c < 4; c++) acc[a][b][c] = 0.f;

    uint2 st[8];
    {
#pragma unroll
        for (int i = 0; i < 8; i++){
            int q = t + i * 256; int r = q >> 6, c4 = q & 63;
            float4 v = *(const float4*)(WA + (size_t)r * 256 + c4 * 4);
            st[i].x = bits2(__floats2bfloat162_rn(v.x, v.y));
            st[i].y = bits2(__floats2bfloat162_rn(v.z, v.w));
        }
    }
#pragma unroll 1
    for (int kc = 0; kc < 8; kc++){
        __nv_bfloat16* dst = sW + (kc & 1) * (32 * SA_S);
#pragma unroll
        for (int i = 0; i < 8; i++){
            int q = t + i * 256; int r = q >> 6, c4 = q & 63;
            *(uint2*)(dst + r * SA_S + c4 * 4) = st[i];
        }
        __syncthreads();
        if (kc < 7){
#pragma unroll
            for (int i = 0; i < 8; i++){
                int q = t + i * 256; int r = q >> 6, c4 = q & 63;
                float4 v = *(const float4*)(WA + (size_t)(kc * 32 + 32 + r) * 256 + c4 * 4);
                st[i].x = bits2(__floats2bfloat162_rn(v.x, v.y));
                st[i].y = bits2(__floats2bfloat162_rn(v.z, v.w));
            }
        }
        unsigned swb = sW_b + (kc & 1) * (32 * SA_S * 2);
#pragma unroll
        for (int ks = 0; ks < 2; ks++){
            unsigned aF2[2][4];
#pragma unroll
            for (int mt = 0; mt < 2; mt++)
                LDSM4(aF2[mt], sA_b + 2 * ((m0 + mt * 16 + (l & 15)) * SA_S
                                           + kc * 32 + ks * 16 + (l >> 4) * 8));
#pragma unroll
            for (int nt2 = 0; nt2 < 8; nt2++){
                unsigned bfr[4];
                LDSM4T(bfr, swb + 2 * ((ks * 16 + (l & 15)) * SA_S
                                        + n0 + nt2 * 16 + (l >> 4) * 8));
#pragma unroll
                for (int mt = 0; mt < 2; mt++){
                    MMA16816(acc[mt][nt2 * 2],     aF2[mt], bfr[0], bfr[1]);
                    MMA16816(acc[mt][nt2 * 2 + 1], aF2[mt], bfr[2], bfr[3]);
                }
            }
        }
    }

    // ---- j epilogue: j = sum_col relu(h+BA)*U ----
    {
        float jp[2][2] = {{0.f,0.f},{0.f,0.f}};
#pragma unroll
        for (int mt = 0; mt < 2; mt++)
#pragma unroll
            for (int nt = 0; nt < 16; nt++){
                int c = n0 + nt * 8 + 2 * (l & 3);
                float ba0 = sBA[c], ba1 = sBA[c + 1];
                float u0 = sU[c],  u1 = sU[c + 1];
                jp[mt][0] += fmaxf(acc[mt][nt][0] + ba0, 0.f) * u0
                           + fmaxf(acc[mt][nt][1] + ba1, 0.f) * u1;
                jp[mt][1] += fmaxf(acc[mt][nt][2] + ba0, 0.f) * u0
                           + fmaxf(acc[mt][nt][3] + ba1, 0.f) * u1;
            }
#pragma unroll
        for (int mt = 0; mt < 2; mt++)
#pragma unroll
            for (int hh = 0; hh < 2; hh++){
                float v = jp[mt][hh];
                v += __shfl_xor_sync(0xffffffffu, v, 1);
                v += __shfl_xor_sync(0xffffffffu, v, 2);
                if ((l & 3) == 0)
                    atomicAdd(&jsm[m0 + mt * 16 + (l >> 2) + hh * 8], v);
            }
    }
    __syncthreads();

    // ---- final epilogue ----
    if (t < 128){
        float mv = (input_uf[row0 + t] != UNUM) ? 1.f : 0.f;
        jsm[t] = mv * expf(jsm[t]);
    }
    __syncthreads();
    if (t < 2){
        float s = 0.f;
#pragma unroll 8
        for (int q = 0; q < 64; q++) s += jsm[t * 64 + q];
        sjv[t] = 1.f / (s + 1e-8f);
    }
    __syncthreads();

    int d = t;
#pragma unroll 1
    for (int bb = 0; bb < 2; bb++){
        int b = 2 * p + bb;
        float fr = 0.f;
#pragma unroll 8
        for (int f = 0; f < 64; f++)
            fr += jsm[bb * 64 + f] * __bfloat162float(sA[(bb * 64 + f) * SA_S + d]);
        fr *= sjv[bb];
        float uidv = g_uid[b * D_ + d];
        float user = uidv + fr;
        float p0 = uidv * E[2 * d]     + user * E[2 * (256 + d)];
        float p1 = uidv * E[2 * d + 1] + user * E[2 * (256 + d) + 1];
        p0 = wred32(p0); p1 = wred32(p1);
        if (l == 0){ rred[w] = p0; rred[8 + w] = p1; }
        __syncthreads();
        if (t == 0){
            float L0 = 0.f, L1 = 0.f;
#pragma unroll
            for (int q = 0; q < 8; q++){ L0 += rred[q]; L1 += rred[8 + q]; }
            float mx = fmaxf(L0, L1);
            float e0 = expf(L0 - mx), e1 = expf(L1 - mx);
            float inv = 1.f / (e0 + e1);
            satt1[0] = e0 * inv; satt1[1] = e1 * inv;
        }
        __syncthreads();
        float ufv = uidv * satt1[0] + user * satt1[1];
        int ii = input_i[b];
        float sc = ufv * iidW[(size_t)ii * D_ + d];
        sc = wred32(sc);
        if (l == 0) rred[w] = sc;
        __syncthreads();
        if (t == 0){
            float s = 0.f;
#pragma unroll
            for (int q = 0; q < 8; q++) s += rred[q];
            out[b] = s + i_bias[ii];
        }
        __syncthreads();
    }
}

// ------------------------------------------------------------------
extern "C" void kernel_launch(void* const* d_in, const int* in_sizes, int n_in,
                              void* d_out, int out_size){
    const int*   input_u  = (const int*)  d_in[0];
    const int*   input_i  = (const int*)  d_in[1];
    const int*   input_uf = (const int*)  d_in[2];
    const float* uidW     = (const float*)d_in[3];
    const float* iidW     = (const float*)d_in[4];
    const float* i_bias   = (const float*)d_in[5];
    const float* Key      = (const float*)d_in[6];
    const float* MemW     = (const float*)d_in[7];
    const float* WA       = (const float*)d_in[8];
    const float* BA       = (const float*)d_in[9];
    const float* Uom      = (const float*)d_in[10];
    const float* E        = (const float*)d_in[11];
    float* out = (float*)d_out;

    size_t sm1 = (size_t)(M_ * KTS + 64 * D_ + 64 * M_) * sizeof(float);

    cudaFuncSetAttribute(k1_att,   cudaFuncAttributeMaxDynamicSharedMemorySize, (int)sm1);
    cudaFuncSetAttribute(k2_fused, cudaFuncAttributeMaxDynamicSharedMemorySize, SMEM_K2);

    k0_prep<<<B_, 256>>>(input_u, uidW);
    k1_att <<<dim3(B_/64, F_), 256, sm1>>>(input_uf, uidW, Key);
    k2_fused<<<B_/2, 256, SMEM_K2>>>(input_uf, input_i, iidW, i_bias,
                                     WA, BA, Uom, E, MemW, out);
}

// round 4
// speedup vs baseline: 4.4004x; 1.7716x over previous
#include <cuda_runtime.h>
#include <cuda_bf16.h>
#include <math.h>

#define UNUM 500000
#define B_ 4096
#define F_ 64
#define D_ 256
#define M_ 32

// ---- scratch ----
__device__ float g_uid [B_*D_];
__device__ float g_uidn[B_*D_];
__device__ float g_colsum[F_*M_];
__device__ float g_eatt[(size_t)B_*F_*M_];           // exp(att_key) 32 MB
__device__ __nv_bfloat16 g_fe[(size_t)B_*F_*D_];     // masked fe bf16, 128 MB
__device__ __nv_bfloat16 g_WAb[65536];               // WA bf16
__device__ __nv_bfloat16 g_Memb[8192];               // Mem bf16

__device__ __forceinline__ float wred32(float v){
#pragma unroll
    for (int o = 16; o; o >>= 1) v += __shfl_xor_sync(0xffffffffu, v, o);
    return v;
}
__device__ __forceinline__ unsigned s2u(const void* p){
    return (unsigned)__cvta_generic_to_shared(p);
}
__device__ __forceinline__ unsigned bits2(__nv_bfloat162 v){
    return *(unsigned*)&v;
}

#define LDSM4(R, addr) asm volatile( \
    "ldmatrix.sync.aligned.m8n8.x4.shared.b16 {%0,%1,%2,%3}, [%4];" \
    : "=r"((R)[0]),"=r"((R)[1]),"=r"((R)[2]),"=r"((R)[3]) : "r"(addr))
#define LDSM4T(R, addr) asm volatile( \
    "ldmatrix.sync.aligned.m8n8.x4.trans.shared.b16 {%0,%1,%2,%3}, [%4];" \
    : "=r"((R)[0]),"=r"((R)[1]),"=r"((R)[2]),"=r"((R)[3]) : "r"(addr))
#define MMA16816(D, A, B0, B1) asm volatile( \
    "mma.sync.aligned.m16n8k16.row.col.f32.bf16.bf16.f32 " \
    "{%0,%1,%2,%3}, {%4,%5,%6,%7}, {%8,%9}, {%0,%1,%2,%3};" \
    : "+f"((D)[0]),"+f"((D)[1]),"+f"((D)[2]),"+f"((D)[3]) \
    : "r"((A)[0]),"r"((A)[1]),"r"((A)[2]),"r"((A)[3]),"r"(B0),"r"(B1))

// ------------------------------------------------------------------
// k_cvt: WA and Mem -> bf16 device globals
// ------------------------------------------------------------------
__global__ void __launch_bounds__(256) k_cvt(const float* __restrict__ WA,
                                             const float* __restrict__ MemW){
    int i = blockIdx.x * 256 + threadIdx.x;   // 0..18431
    if (i < 16384){
        float4 v = ((const float4*)WA)[i];
        uint2 u;
        u.x = bits2(__floats2bfloat162_rn(v.x, v.y));
        u.y = bits2(__floats2bfloat162_rn(v.z, v.w));
        ((uint2*)g_WAb)[i] = u;
    } else if (i < 18432){
        int q = i - 16384;
        float4 v = ((const float4*)MemW)[q];
        uint2 u;
        u.x = bits2(__floats2bfloat162_rn(v.x, v.y));
        u.y = bits2(__floats2bfloat162_rn(v.z, v.w));
        ((uint2*)g_Memb)[q] = u;
    }
}

// ------------------------------------------------------------------
// K0: uid gather + l2 norm, zero colsum
// ------------------------------------------------------------------
__global__ void __launch_bounds__(256) k0_prep(const int* __restrict__ input_u,
                                               const float* __restrict__ uidW){
    int b = blockIdx.x, t = threadIdx.x;
    int u = input_u[b];
    float v = uidW[(size_t)u * D_ + t];
    __shared__ float red[8];
    __shared__ float invs;
    float s = wred32(v * v);
    if ((t & 31) == 0) red[t >> 5] = s;
    __syncthreads();
    if (t == 0){
        float x = 0.f;
#pragma unroll
        for (int i = 0; i < 8; i++) x += red[i];
        invs = 1.f / fmaxf(sqrtf(x), 1e-12f);
    }
    __syncthreads();
    g_uid [b * D_ + t] = v;
    g_uidn[b * D_ + t] = v * invs;
    if (b < 8) g_colsum[b * 256 + t] = 0.f;
}

// ------------------------------------------------------------------
// K1: fe gather (MLP-batched) -> masked fe bf16 -> cross bf16 ->
//     att_key via MMA -> exp -> g_eatt + colsum atomics
// ------------------------------------------------------------------
#define KBS 40
#define CBS 264
__global__ void __launch_bounds__(256,2) k1_att(const int* __restrict__ input_uf,
                                                const float* __restrict__ uidW,
                                                const float* __restrict__ Key){
    extern __shared__ char smraw[];
    __nv_bfloat16* Kb  = (__nv_bfloat16*)smraw;        // [256][40]
    __nv_bfloat16* crs = Kb + 256 * KBS;               // [64][264]
    float* eat = (float*)(crs + 64 * CBS);             // [64][36]
    int t = threadIdx.x, f = blockIdx.y;
    int bbase = blockIdx.x * 64;
    int w = t >> 5, l = t & 31;

    for (int i = t; i < 8192; i += 256){
        int d = i >> 5, m = i & 31;
        Kb[d * KBS + m] = __float2bfloat16(Key[i]);
    }

    int ufs[8];
#pragma unroll
    for (int rr = 0; rr < 8; rr++)
        ufs[rr] = input_uf[(bbase + w * 8 + rr) * F_ + f];

#pragma unroll
    for (int g = 0; g < 2; g++){
        float4 A0[4], A1[4];
#pragma unroll
        for (int q = 0; q < 4; q++){
            const float4* fp = (const float4*)(uidW + (size_t)ufs[g * 4 + q] * D_);
            A0[q] = fp[l]; A1[q] = fp[32 + l];
        }
#pragma unroll
        for (int q = 0; q < 4; q++){
            int r = w * 8 + g * 4 + q, b = bbase + r;
            float msk = (ufs[g * 4 + q] != UNUM) ? 1.f : 0.f;
            float4 a0 = A0[q], a1 = A1[q];
            a0.x *= msk; a0.y *= msk; a0.z *= msk; a0.w *= msk;
            a1.x *= msk; a1.y *= msk; a1.z *= msk; a1.w *= msk;
            {   // store masked fe bf16
                uint2 u0, u1;
                u0.x = bits2(__floats2bfloat162_rn(a0.x, a0.y));
                u0.y = bits2(__floats2bfloat162_rn(a0.z, a0.w));
                u1.x = bits2(__floats2bfloat162_rn(a1.x, a1.y));
                u1.y = bits2(__floats2bfloat162_rn(a1.z, a1.w));
                size_t rowg = ((size_t)b * F_ + f) * D_;
                *(uint2*)(g_fe + rowg + l * 4)       = u0;
                *(uint2*)(g_fe + rowg + 128 + l * 4) = u1;
            }
            float ss = a0.x*a0.x + a0.y*a0.y + a0.z*a0.z + a0.w*a0.w
                     + a1.x*a1.x + a1.y*a1.y + a1.z*a1.z + a1.w*a1.w;
            ss = wred32(ss);
            float inv = 1.f / fmaxf(sqrtf(ss), 1e-12f);
            const float4* up = (const float4*)(g_uidn + (size_t)b * D_);
            float4 v0 = up[l], v1 = up[32 + l];
            uint2 cu0, cu1;
            cu0.x = bits2(__floats2bfloat162_rn(a0.x*inv*v0.x, a0.y*inv*v0.y));
            cu0.y = bits2(__floats2bfloat162_rn(a0.z*inv*v0.z, a0.w*inv*v0.w));
            cu1.x = bits2(__floats2bfloat162_rn(a1.x*inv*v1.x, a1.y*inv*v1.y));
            cu1.y = bits2(__floats2bfloat162_rn(a1.z*inv*v1.z, a1.w*inv*v1.w));
            *(uint2*)(crs + r * CBS + l * 4)       = cu0;
            *(uint2*)(crs + r * CBS + 128 + l * 4) = cu1;
        }
    }
    __syncthreads();

    // MMA phase: warp = (mt 0..3) x (hf 0..1); 16 rows x 16 cols each
    {
        int mt = w & 3, hf = w >> 2;
        float acc[2][4];
#pragma unroll
        for (int a = 0; a < 2; a++)
#pragma unroll
            for (int c = 0; c < 4; c++) acc[a][c] = 0.f;
        unsigned crs_b = s2u(crs), kb_b = s2u(Kb);
#pragma unroll
        for (int ks = 0; ks < 16; ks++){
            unsigned aF[4], bF[4];
            LDSM4(aF, crs_b + 2 * ((mt * 16 + (l & 15)) * CBS + ks * 16 + (l >> 4) * 8));
            LDSM4T(bF, kb_b + 2 * ((ks * 16 + (l & 15)) * KBS + hf * 16 + (l >> 4) * 8));
            MMA16816(acc[0], aF, bF[0], bF[1]);
            MMA16816(acc[1], aF, bF[2], bF[3]);
        }
#pragma unroll
        for (int ntl = 0; ntl < 2; ntl++){
            int c = hf * 16 + ntl * 8 + 2 * (l & 3);
            int r = mt * 16 + (l >> 2);
            eat[r * 36 + c]           = expf(acc[ntl][0]);
            eat[r * 36 + c + 1]       = expf(acc[ntl][1]);
            eat[(r + 8) * 36 + c]     = expf(acc[ntl][2]);
            eat[(r + 8) * 36 + c + 1] = expf(acc[ntl][3]);
        }
    }
    __syncthreads();

    for (int i = t; i < 2048; i += 256){
        int r = i >> 5, m = i & 31;
        g_eatt[((size_t)(bbase + r) * F_ + f) * M_ + m] = eat[r * 36 + m];
    }
    if (t < M_){
        float s = 0.f;
#pragma unroll 8
        for (int r = 0; r < 64; r++) s += eat[r * 36 + t];
        atomicAdd(&g_colsum[f * M_ + t], s);
    }
}

// ------------------------------------------------------------------
// K2 fused (512 thr): attmem -> f1 (MMA) -> f2 (smem) -> h = f2@WA
//                     (MMA, streamed) -> j -> friend -> score
// ------------------------------------------------------------------
#define SA_S  264
#define SAT_S 40
#define OFF_SA   0
#define OFF_SW   67584
#define OFF_SMEM 101376
#define OFF_SATT 118272
#define OFF_SCS  128512
#define OFF_SBA  136704
#define OFF_SU   137728
#define OFF_JSM  138752
#define OFF_RED  139264
#define SMEM_K2  139520

__global__ void __launch_bounds__(512,1) k2_fused(
        const int* __restrict__ input_uf, const int* __restrict__ input_i,
        const float* __restrict__ iidW, const float* __restrict__ i_bias,
        const float* __restrict__ BA, const float* __restrict__ Uom,
        const float* __restrict__ E, float* __restrict__ out){
    extern __shared__ char smraw[];
    __nv_bfloat16* sA   = (__nv_bfloat16*)(smraw + OFF_SA);    // [128][264]
    __nv_bfloat16* sW   = (__nv_bfloat16*)(smraw + OFF_SW);    // 2 x [32][264]
    __nv_bfloat16* sMm  = (__nv_bfloat16*)(smraw + OFF_SMEM);  // [32][264]
    __nv_bfloat16* sAtt = (__nv_bfloat16*)(smraw + OFF_SATT);  // [128][40]
    float* scs  = (float*)(smraw + OFF_SCS);                   // [2048]
    float* sBA  = (float*)(smraw + OFF_SBA);                   // [256]
    float* sU   = (float*)(smraw + OFF_SU);                    // [256]
    float* jsm  = (float*)(smraw + OFF_JSM);                   // [128]
    float* r0s  = (float*)(smraw + OFF_RED);                   // [16]
    float* r1s  = r0s + 16;                                    // [16]
    float* a0s  = r1s + 16;                                    // [2]
    float* a1s  = a0s + 2;                                     // [2]
    float* sjv  = a1s + 2;                                     // [2]

    int t = threadIdx.x, p = blockIdx.x;
    int w = t >> 5, l = t & 31;
    size_t row0 = (size_t)p * 128;

    // ---- loads ----
    {
        const uint4* src = (const uint4*)(g_fe + row0 * D_);
#pragma unroll
        for (int i = 0; i < 8; i++){
            int q = t + i * 512; int r = q >> 5, c = q & 31;
            *(uint4*)(sA + r * SA_S + c * 8) = src[q];
        }
    }
    {
        const uint4* src = (const uint4*)g_Memb;
#pragma unroll
        for (int i = 0; i < 2; i++){
            int q = t + i * 512; int r = q >> 5, c = q & 31;
            *(uint4*)(sMm + r * SA_S + c * 8) = src[q];
        }
    }
#pragma unroll
    for (int i = t; i < 2048; i += 512) scs[i] = 1.f / g_colsum[i];
    if (t < 256){ sBA[t] = BA[t]; sU[t] = Uom[t]; }
    if (t < 128) jsm[t] = 0.f;
    __syncthreads();
    {
#pragma unroll
        for (int i = 0; i < 8; i++){
            int q = t + i * 512; int r = q >> 5, m = q & 31;
            sAtt[r * SAT_S + m] = __float2bfloat16(
                g_eatt[(row0 + r) * M_ + m] * scs[(r & 63) * 32 + m]);
        }
    }
    __syncthreads();

    int mw = w & 3, nw = w >> 2;
    int m0 = mw * 32, n0 = nw * 64;
    unsigned sA_b   = s2u(sA);
    unsigned sMm_b  = s2u(sMm);
    unsigned sAtt_b = s2u(sAtt);
    unsigned sW_b   = s2u(sW);

    // ---- GEMM1: f1 = attmem @ Mem ; fold f2 = f1 * fe into sA ----
    {
        unsigned aF[2][2][4];
#pragma unroll
        for (int mt = 0; mt < 2; mt++)
#pragma unroll
            for (int ks = 0; ks < 2; ks++)
                LDSM4(aF[mt][ks], sAtt_b + 2 * ((m0 + mt * 16 + (l & 15)) * SAT_S
                                                + ks * 16 + (l >> 4) * 8));
#pragma unroll
        for (int nt2 = 0; nt2 < 4; nt2++){
            float a1c[2][2][4];
#pragma unroll
            for (int a = 0; a < 2; a++)
#pragma unroll
                for (int bq = 0; bq < 2; bq++)
#pragma unroll
                    for (int c = 0; c < 4; c++) a1c[a][bq][c] = 0.f;
#pragma unroll
            for (int ks = 0; ks < 2; ks++){
                unsigned bfr[4];
                LDSM4T(bfr, sMm_b + 2 * ((ks * 16 + (l & 15)) * SA_S
                                          + n0 + nt2 * 16 + (l >> 4) * 8));
#pragma unroll
                for (int mt = 0; mt < 2; mt++){
                    MMA16816(a1c[mt][0], aF[mt][ks], bfr[0], bfr[1]);
                    MMA16816(a1c[mt][1], aF[mt][ks], bfr[2], bfr[3]);
                }
            }
#pragma unroll
            for (int mt = 0; mt < 2; mt++)
#pragma unroll
                for (int ntl = 0; ntl < 2; ntl++){
                    int r1 = m0 + mt * 16 + (l >> 2);
                    int c  = n0 + (nt2 * 2 + ntl) * 8 + 2 * (l & 3);
                    __nv_bfloat162* p0 = (__nv_bfloat162*)(sA + r1 * SA_S + c);
                    float2 fe0 = __bfloat1622float2(*p0);
                    *p0 = __floats2bfloat162_rn(a1c[mt][ntl][0] * fe0.x,
                                                a1c[mt][ntl][1] * fe0.y);
                    __nv_bfloat162* p1 = (__nv_bfloat162*)(sA + (r1 + 8) * SA_S + c);
                    float2 fe1 = __bfloat1622float2(*p1);
                    *p1 = __floats2bfloat162_rn(a1c[mt][ntl][2] * fe1.x,
                                                a1c[mt][ntl][3] * fe1.y);
                }
        }
    }
    __syncthreads();

    // ---- GEMM2: h = f2 @ WA (streamed bf16 WA) ----
    float acc[2][8][4];
#pragma unroll
    for (int a = 0; a < 2; a++)
#pragma unroll
        for (int b = 0; b < 8; b++)
#pragma unroll
            for (int c = 0; c < 4; c++) acc[a][b][c] = 0.f;

    uint4 st[2];
#pragma unroll
    for (int i = 0; i < 2; i++) st[i] = ((const uint4*)g_WAb)[t + i * 512];

#pragma unroll 1
    for (int kc = 0; kc < 8; kc++){
        __nv_bfloat16* dst = sW + (kc & 1) * (32 * SA_S);
#pragma unroll
        for (int i = 0; i < 2; i++){
            int q = t + i * 512; int r = q >> 5, c = q & 31;
            *(uint4*)(dst + r * SA_S + c * 8) = st[i];
        }
        __syncthreads();
        if (kc < 7){
#pragma unroll
            for (int i = 0; i < 2; i++)
                st[i] = ((const uint4*)g_WAb)[(kc + 1) * 1024 + t + i * 512];
        }
        unsigned swb = sW_b + (kc & 1) * (32 * SA_S * 2);
#pragma unroll
        for (int ks = 0; ks < 2; ks++){
            unsigned aF2[2][4];
#pragma unroll
            for (int mt = 0; mt < 2; mt++)
                LDSM4(aF2[mt], sA_b + 2 * ((m0 + mt * 16 + (l & 15)) * SA_S
                                           + kc * 32 + ks * 16 + (l >> 4) * 8));
#pragma unroll
            for (int nt2 = 0; nt2 < 4; nt2++){
                unsigned bfr[4];
                LDSM4T(bfr, swb + 2 * ((ks * 16 + (l & 15)) * SA_S
                                        + n0 + nt2 * 16 + (l >> 4) * 8));
#pragma unroll
                for (int mt = 0; mt < 2; mt++){
                    MMA16816(acc[mt][nt2 * 2],     aF2[mt], bfr[0], bfr[1]);
                    MMA16816(acc[mt][nt2 * 2 + 1], aF2[mt], bfr[2], bfr[3]);
                }
            }
        }
    }

    // ---- j epilogue ----
    {
        float jp[2][2] = {{0.f,0.f},{0.f,0.f}};
#pragma unroll
        for (int mt = 0; mt < 2; mt++)
#pragma unroll
            for (int nt = 0; nt < 8; nt++){
                int c = n0 + nt * 8 + 2 * (l & 3);
                float ba0 = sBA[c], ba1 = sBA[c + 1];
                float u0 = sU[c],  u1 = sU[c + 1];
                jp[mt][0] += fmaxf(acc[mt][nt][0] + ba0, 0.f) * u0
                           + fmaxf(acc[mt][nt][1] + ba1, 0.f) * u1;
                jp[mt][1] += fmaxf(acc[mt][nt][2] + ba0, 0.f) * u0
                           + fmaxf(acc[mt][nt][3] + ba1, 0.f) * u1;
            }
#pragma unroll
        for (int mt = 0; mt < 2; mt++)
#pragma unroll
            for (int hh = 0; hh < 2; hh++){
                float v = jp[mt][hh];
                v += __shfl_xor_sync(0xffffffffu, v, 1);
                v += __shfl_xor_sync(0xffffffffu, v, 2);
                if ((l & 3) == 0)
                    atomicAdd(&jsm[m0 + mt * 16 + (l >> 2) + hh * 8], v);
            }
    }
    __syncthreads();

    if (t < 128){
        float mv = (input_uf[row0 + t] != UNUM) ? 1.f : 0.f;
        jsm[t] = mv * expf(jsm[t]);
    }
    __syncthreads();
    if (t < 2){
        float s = 0.f;
#pragma unroll 8
        for (int q = 0; q < 64; q++) s += jsm[t * 64 + q];
        sjv[t] = 1.f / (s + 1e-8f);
    }
    __syncthreads();

    // ---- final epilogue: 512 threads = 2 b x 256 d ----
    int bb = t >> 8, d = t & 255, b = 2 * p + bb;
    float fr = 0.f;
#pragma unroll 8
    for (int ff = 0; ff < 64; ff++)
        fr += jsm[bb * 64 + ff] * __bfloat162float(sA[(bb * 64 + ff) * SA_S + d]);
    fr *= sjv[bb];
    float uidv = g_uid[b * D_ + d];
    float user = uidv + fr;
    float p0 = uidv * E[2 * d]     + user * E[2 * (256 + d)];
    float p1 = uidv * E[2 * d + 1] + user * E[2 * (256 + d) + 1];
    p0 = wred32(p0); p1 = wred32(p1);
    if (l == 0){ r0s[w] = p0; r1s[w] = p1; }
    __syncthreads();
    if (t < 2){
        float L0 = 0.f, L1 = 0.f;
#pragma unroll
        for (int q = 0; q < 8; q++){ L0 += r0s[t * 8 + q]; L1 += r1s[t * 8 + q]; }
        float mx = fmaxf(L0, L1);
        float e0 = expf(L0 - mx), e1 = expf(L1 - mx);
        float inv = 1.f / (e0 + e1);
        a0s[t] = e0 * inv; a1s[t] = e1 * inv;
    }
    __syncthreads();
    float ufv = uidv * a0s[bb] + user * a1s[bb];
    int ii = input_i[b];
    float sc = ufv * iidW[(size_t)ii * D_ + d];
    sc = wred32(sc);
    if (l == 0) r0s[w] = sc;
    __syncthreads();
    if (t < 2){
        float s = 0.f;
#pragma unroll
        for (int q = 0; q < 8; q++) s += r0s[t * 8 + q];
        out[2 * p + t] = s + i_bias[input_i[2 * p + t]];
    }
}

// ------------------------------------------------------------------
extern "C" void kernel_launch(void* const* d_in, const int* in_sizes, int n_in,
                              void* d_out, int out_size){
    const int*   input_u  = (const int*)  d_in[0];
    const int*   input_i  = (const int*)  d_in[1];
    const int*   input_uf = (const int*)  d_in[2];
    const float* uidW     = (const float*)d_in[3];
    const float* iidW     = (const float*)d_in[4];
    const float* i_bias   = (const float*)d_in[5];
    const float* Key      = (const float*)d_in[6];
    const float* MemW     = (const float*)d_in[7];
    const float* WA       = (const float*)d_in[8];
    const float* BA       = (const float*)d_in[9];
    const float* Uom      = (const float*)d_in[10];
    const float* E        = (const float*)d_in[11];
    float* out = (float*)d_out;

    size_t sm1 = (size_t)(256*KBS*2 + 64*CBS*2 + 64*36*4);   // ~63.5 KB

    cudaFuncSetAttribute(k1_att,   cudaFuncAttributeMaxDynamicSharedMemorySize, (int)sm1);
    cudaFuncSetAttribute(k2_fused, cudaFuncAttributeMaxDynamicSharedMemorySize, SMEM_K2);

    k_cvt<<<72, 256>>>(WA, MemW);
    k0_prep<<<B_, 256>>>(input_u, uidW);
    k1_att <<<dim3(B_/64, F_), 256, sm1>>>(input_uf, uidW, Key);
    k2_fused<<<B_/2, 512, SMEM_K2>>>(input_uf, input_i, iidW, i_bias,
                                     BA, Uom, E, out);
}

// round 5
// speedup vs baseline: 5.0340x; 1.1440x over previous
#include <cuda_runtime.h>
#include <cuda_bf16.h>
#include <math.h>

#define UNUM 500000
#define B_ 4096
#define F_ 64
#define D_ 256
#define M_ 32

// ---- scratch ----
__device__ float g_uid [B_*D_];
__device__ float g_uidn[B_*D_];
__device__ float g_colsum[F_*M_];                    // after k1b: 1/colsum
__device__ float g_eatt[(size_t)B_*F_*M_];           // exp(att_key) 32 MB
__device__ __nv_bfloat16 g_fe[(size_t)B_*F_*D_];     // masked fe bf16, 128 MB
__device__ __nv_bfloat16 g_WAb[65536];               // WA bf16
__device__ __nv_bfloat16 g_Memb[8192];               // Mem bf16

__device__ __forceinline__ float wred32(float v){
#pragma unroll
    for (int o = 16; o; o >>= 1) v += __shfl_xor_sync(0xffffffffu, v, o);
    return v;
}
__device__ __forceinline__ unsigned s2u(const void* p){
    return (unsigned)__cvta_generic_to_shared(p);
}
__device__ __forceinline__ unsigned bits2(__nv_bfloat162 v){
    return *(unsigned*)&v;
}

#define LDSM4(R, addr) asm volatile( \
    "ldmatrix.sync.aligned.m8n8.x4.shared.b16 {%0,%1,%2,%3}, [%4];" \
    : "=r"((R)[0]),"=r"((R)[1]),"=r"((R)[2]),"=r"((R)[3]) : "r"(addr))
#define LDSM4T(R, addr) asm volatile( \
    "ldmatrix.sync.aligned.m8n8.x4.trans.shared.b16 {%0,%1,%2,%3}, [%4];" \
    : "=r"((R)[0]),"=r"((R)[1]),"=r"((R)[2]),"=r"((R)[3]) : "r"(addr))
#define MMA16816(D, A, B0, B1) asm volatile( \
    "mma.sync.aligned.m16n8k16.row.col.f32.bf16.bf16.f32 " \
    "{%0,%1,%2,%3}, {%4,%5,%6,%7}, {%8,%9}, {%0,%1,%2,%3};" \
    : "+f"((D)[0]),"+f"((D)[1]),"+f"((D)[2]),"+f"((D)[3]) \
    : "r"((A)[0]),"r"((A)[1]),"r"((A)[2]),"r"((A)[3]),"r"(B0),"r"(B1))

// ------------------------------------------------------------------
// k_cvt: WA and Mem -> bf16 device globals
// ------------------------------------------------------------------
__global__ void __launch_bounds__(256) k_cvt(const float* __restrict__ WA,
                                             const float* __restrict__ MemW){
    int i = blockIdx.x * 256 + threadIdx.x;
    if (i < 16384){
        float4 v = ((const float4*)WA)[i];
        uint2 u;
        u.x = bits2(__floats2bfloat162_rn(v.x, v.y));
        u.y = bits2(__floats2bfloat162_rn(v.z, v.w));
        ((uint2*)g_WAb)[i] = u;
    } else if (i < 18432){
        int q = i - 16384;
        float4 v = ((const float4*)MemW)[q];
        uint2 u;
        u.x = bits2(__floats2bfloat162_rn(v.x, v.y));
        u.y = bits2(__floats2bfloat162_rn(v.z, v.w));
        ((uint2*)g_Memb)[q] = u;
    }
}

// ------------------------------------------------------------------
// K0: uid gather + l2 norm, zero colsum
// ------------------------------------------------------------------
__global__ void __launch_bounds__(256) k0_prep(const int* __restrict__ input_u,
                                               const float* __restrict__ uidW){
    int b = blockIdx.x, t = threadIdx.x;
    int u = input_u[b];
    float v = uidW[(size_t)u * D_ + t];
    __shared__ float red[8];
    __shared__ float invs;
    float s = wred32(v * v);
    if ((t & 31) == 0) red[t >> 5] = s;
    __syncthreads();
    if (t == 0){
        float x = 0.f;
#pragma unroll
        for (int i = 0; i < 8; i++) x += red[i];
        invs = 1.f / fmaxf(sqrtf(x), 1e-12f);
    }
    __syncthreads();
    g_uid [b * D_ + t] = v;
    g_uidn[b * D_ + t] = v * invs;
    if (b < 8) g_colsum[b * 256 + t] = 0.f;
}

// ------------------------------------------------------------------
// K1: fe gather (MLP-batched) -> masked fe bf16 -> cross bf16 ->
//     att_key via MMA -> exp -> g_eatt + colsum atomics
// ------------------------------------------------------------------
#define KBS 40
#define CBS 264
__global__ void __launch_bounds__(256,3) k1_att(const int* __restrict__ input_uf,
                                                const float* __restrict__ uidW,
                                                const float* __restrict__ Key){
    extern __shared__ char smraw[];
    __nv_bfloat16* Kb  = (__nv_bfloat16*)smraw;        // [256][40]
    __nv_bfloat16* crs = Kb + 256 * KBS;               // [64][264]
    float* eat = (float*)(crs + 64 * CBS);             // [64][36]
    int t = threadIdx.x, f = blockIdx.y;
    int bbase = blockIdx.x * 64;
    int w = t >> 5, l = t & 31;

    for (int i = t; i < 8192; i += 256){
        int d = i >> 5, m = i & 31;
        Kb[d * KBS + m] = __float2bfloat16(Key[i]);
    }

    int ufs[8];
#pragma unroll
    for (int rr = 0; rr < 8; rr++)
        ufs[rr] = input_uf[(bbase + w * 8 + rr) * F_ + f];

#pragma unroll
    for (int g = 0; g < 2; g++){
        float4 A0[4], A1[4];
#pragma unroll
        for (int q = 0; q < 4; q++){
            const float4* fp = (const float4*)(uidW + (size_t)ufs[g * 4 + q] * D_);
            A0[q] = fp[l]; A1[q] = fp[32 + l];
        }
#pragma unroll
        for (int q = 0; q < 4; q++){
            int r = w * 8 + g * 4 + q, b = bbase + r;
            float msk = (ufs[g * 4 + q] != UNUM) ? 1.f : 0.f;
            float4 a0 = A0[q], a1 = A1[q];
            a0.x *= msk; a0.y *= msk; a0.z *= msk; a0.w *= msk;
            a1.x *= msk; a1.y *= msk; a1.z *= msk; a1.w *= msk;
            {
                uint2 u0, u1;
                u0.x = bits2(__floats2bfloat162_rn(a0.x, a0.y));
                u0.y = bits2(__floats2bfloat162_rn(a0.z, a0.w));
                u1.x = bits2(__floats2bfloat162_rn(a1.x, a1.y));
                u1.y = bits2(__floats2bfloat162_rn(a1.z, a1.w));
                size_t rowg = ((size_t)b * F_ + f) * D_;
                *(uint2*)(g_fe + rowg + l * 4)       = u0;
                *(uint2*)(g_fe + rowg + 128 + l * 4) = u1;
            }
            float ss = a0.x*a0.x + a0.y*a0.y + a0.z*a0.z + a0.w*a0.w
                     + a1.x*a1.x + a1.y*a1.y + a1.z*a1.z + a1.w*a1.w;
            ss = wred32(ss);
            float inv = 1.f / fmaxf(sqrtf(ss), 1e-12f);
            const float4* up = (const float4*)(g_uidn + (size_t)b * D_);
            float4 v0 = up[l], v1 = up[32 + l];
            uint2 cu0, cu1;
            cu0.x = bits2(__floats2bfloat162_rn(a0.x*inv*v0.x, a0.y*inv*v0.y));
            cu0.y = bits2(__floats2bfloat162_rn(a0.z*inv*v0.z, a0.w*inv*v0.w));
            cu1.x = bits2(__floats2bfloat162_rn(a1.x*inv*v1.x, a1.y*inv*v1.y));
            cu1.y = bits2(__floats2bfloat162_rn(a1.z*inv*v1.z, a1.w*inv*v1.w));
            *(uint2*)(crs + r * CBS + l * 4)       = cu0;
            *(uint2*)(crs + r * CBS + 128 + l * 4) = cu1;
        }
    }
    __syncthreads();

    {
        int mt = w & 3, hf = w >> 2;
        float acc[2][4];
#pragma unroll
        for (int a = 0; a < 2; a++)
#pragma unroll
            for (int c = 0; c < 4; c++) acc[a][c] = 0.f;
        unsigned crs_b = s2u(crs), kb_b = s2u(Kb);
#pragma unroll
        for (int ks = 0; ks < 16; ks++){
            unsigned aF[4], bF[4];
            LDSM4(aF, crs_b + 2 * ((mt * 16 + (l & 15)) * CBS + ks * 16 + (l >> 4) * 8));
            LDSM4T(bF, kb_b + 2 * ((ks * 16 + (l & 15)) * KBS + hf * 16 + (l >> 4) * 8));
            MMA16816(acc[0], aF, bF[0], bF[1]);
            MMA16816(acc[1], aF, bF[2], bF[3]);
        }
#pragma unroll
        for (int ntl = 0; ntl < 2; ntl++){
            int c = hf * 16 + ntl * 8 + 2 * (l & 3);
            int r = mt * 16 + (l >> 2);
            eat[r * 36 + c]           = expf(acc[ntl][0]);
            eat[r * 36 + c + 1]       = expf(acc[ntl][1]);
            eat[(r + 8) * 36 + c]     = expf(acc[ntl][2]);
            eat[(r + 8) * 36 + c + 1] = expf(acc[ntl][3]);
        }
    }
    __syncthreads();

    for (int i = t; i < 2048; i += 256){
        int r = i >> 5, m = i & 31;
        g_eatt[((size_t)(bbase + r) * F_ + f) * M_ + m] = eat[r * 36 + m];
    }
    if (t < M_){
        float s = 0.f;
#pragma unroll 8
        for (int r = 0; r < 64; r++) s += eat[r * 36 + t];
        atomicAdd(&g_colsum[f * M_ + t], s);
    }
}

// ------------------------------------------------------------------
// K1b: invert colsum in place
// ------------------------------------------------------------------
__global__ void __launch_bounds__(256) k1b_inv(){
    int i = blockIdx.x * 256 + threadIdx.x;
    g_colsum[i] = 1.f / g_colsum[i];
}

// ------------------------------------------------------------------
// K2 fused (512 thr, 2 CTA/SM): attmem -> f1 (MMA) -> f2 (smem) ->
//   GEMM2 N-panel-outer/K-inner (16-reg acc) -> j -> friend -> score
// ------------------------------------------------------------------
#define SA_S  264
#define SAT_S 40
#define WPS   72          // WA panel row stride (bf16)
#define OFF_SA   0        // [128][264] bf16 : fe -> f2
#define OFF_SWP  67584    // 2 x [64][72] bf16 WA panels ; unions Mem [32][264]
#define OFF_SATT 86016    // [128][40] bf16 attmem
#define OFF_SBA  96256    // [256] f32
#define OFF_SU   97280    // [256] f32
#define OFF_JSM  98304    // [128] f32
#define OFF_RED  98816    // reductions
#define SMEM_K2  99328

__global__ void __launch_bounds__(512,2) k2_fused(
        const int* __restrict__ input_uf, const int* __restrict__ input_i,
        const float* __restrict__ iidW, const float* __restrict__ i_bias,
        const float* __restrict__ BA, const float* __restrict__ Uom,
        const float* __restrict__ E, float* __restrict__ out){
    extern __shared__ char smraw[];
    __nv_bfloat16* sA   = (__nv_bfloat16*)(smraw + OFF_SA);
    __nv_bfloat16* sWP  = (__nv_bfloat16*)(smraw + OFF_SWP);
    __nv_bfloat16* sMm  = (__nv_bfloat16*)(smraw + OFF_SWP);   // union
    __nv_bfloat16* sAtt = (__nv_bfloat16*)(smraw + OFF_SATT);
    float* sBA  = (float*)(smraw + OFF_SBA);
    float* sU   = (float*)(smraw + OFF_SU);
    float* jsm  = (float*)(smraw + OFF_JSM);
    float* r0s  = (float*)(smraw + OFF_RED);                   // [16]
    float* r1s  = r0s + 16;                                    // [16]
    float* a0s  = r1s + 16;                                    // [2]
    float* a1s  = a0s + 2;                                     // [2]
    float* sjv  = a1s + 2;                                     // [2]

    int t = threadIdx.x, p = blockIdx.x;
    int w = t >> 5, l = t & 31;
    size_t row0 = (size_t)p * 128;

    // ---- loads ----
    {
        const uint4* src = (const uint4*)(g_fe + row0 * D_);
#pragma unroll
        for (int i = 0; i < 8; i++){
            int q = t + i * 512; int r = q >> 5, c = q & 31;
            *(uint4*)(sA + r * SA_S + c * 8) = src[q];
        }
    }
    {
        const uint4* src = (const uint4*)g_Memb;
#pragma unroll
        for (int i = 0; i < 2; i++){
            int q = t + i * 512; int r = q >> 5, c = q & 31;
            *(uint4*)(sMm + r * SA_S + c * 8) = src[q];
        }
    }
    if (t < 256){ sBA[t] = BA[t]; sU[t] = Uom[t]; }
    if (t < 128) jsm[t] = 0.f;
    {
#pragma unroll
        for (int i = 0; i < 8; i++){
            int q = t + i * 512; int r = q >> 5, m = q & 31;
            sAtt[r * SAT_S + m] = __float2bfloat16(
                g_eatt[(row0 + r) * M_ + m] * g_colsum[(r & 63) * 32 + m]);
        }
    }
    // prefetch first WA chunk (np=0,kc=0) into regs
    uint4 st = *(const uint4*)(g_WAb + (size_t)(t >> 3) * 256 + (t & 7) * 8);
    __syncthreads();

    unsigned sA_b   = s2u(sA);
    unsigned sMm_b  = s2u(sMm);
    unsigned sAtt_b = s2u(sAtt);
    unsigned sWP_b  = s2u(sWP);

    // ---- GEMM1: f1 = attmem @ Mem ; fold f2 = f1 * fe into sA ----
    {
        int mw = w & 3, nw = w >> 2;
        int m0 = mw * 32, n0 = nw * 64;
        unsigned aF[2][2][4];
#pragma unroll
        for (int mt = 0; mt < 2; mt++)
#pragma unroll
            for (int ks = 0; ks < 2; ks++)
                LDSM4(aF[mt][ks], sAtt_b + 2 * ((m0 + mt * 16 + (l & 15)) * SAT_S
                                                + ks * 16 + (l >> 4) * 8));
#pragma unroll
        for (int nt2 = 0; nt2 < 4; nt2++){
            float a1c[2][2][4];
#pragma unroll
            for (int a = 0; a < 2; a++)
#pragma unroll
                for (int bq = 0; bq < 2; bq++)
#pragma unroll
                    for (int c = 0; c < 4; c++) a1c[a][bq][c] = 0.f;
#pragma unroll
            for (int ks = 0; ks < 2; ks++){
                unsigned bfr[4];
                LDSM4T(bfr, sMm_b + 2 * ((ks * 16 + (l & 15)) * SA_S
                                          + n0 + nt2 * 16 + (l >> 4) * 8));
#pragma unroll
                for (int mt = 0; mt < 2; mt++){
                    MMA16816(a1c[mt][0], aF[mt][ks], bfr[0], bfr[1]);
                    MMA16816(a1c[mt][1], aF[mt][ks], bfr[2], bfr[3]);
                }
            }
#pragma unroll
            for (int mt = 0; mt < 2; mt++)
#pragma unroll
                for (int ntl = 0; ntl < 2; ntl++){
                    int r1 = m0 + mt * 16 + (l >> 2);
                    int c  = n0 + (nt2 * 2 + ntl) * 8 + 2 * (l & 3);
                    __nv_bfloat162* p0 = (__nv_bfloat162*)(sA + r1 * SA_S + c);
                    float2 fe0 = __bfloat1622float2(*p0);
                    *p0 = __floats2bfloat162_rn(a1c[mt][ntl][0] * fe0.x,
                                                a1c[mt][ntl][1] * fe0.y);
                    __nv_bfloat162* p1 = (__nv_bfloat162*)(sA + (r1 + 8) * SA_S + c);
                    float2 fe1 = __bfloat1622float2(*p1);
                    *p1 = __floats2bfloat162_rn(a1c[mt][ntl][2] * fe1.x,
                                                a1c[mt][ntl][3] * fe1.y);
                }
        }
    }
    __syncthreads();

    // ---- GEMM2: h = f2 @ WA ; N-panel outer, K inner; j folded ----
    int m0g = (w & 7) * 16;
    int n0p = (w >> 3) * 32;
    float jp[2] = {0.f, 0.f};
    float acc[4][4];
#pragma unroll
    for (int a = 0; a < 4; a++)
#pragma unroll
        for (int c = 0; c < 4; c++) acc[a][c] = 0.f;

#pragma unroll 1
    for (int u = 0; u < 16; u++){
        int np = u >> 2, kc = u & 3;
        // store prefetched chunk
        *(uint4*)(sWP + (u & 1) * (64 * WPS) + (t >> 3) * WPS + (t & 7) * 8) = st;
        __syncthreads();
        // prefetch next
        if (u < 15){
            int u2 = u + 1, np2 = u2 >> 2, kc2 = u2 & 3;
            st = *(const uint4*)(g_WAb + (size_t)(kc2 * 64 + (t >> 3)) * 256
                                 + np2 * 64 + (t & 7) * 8);
        }
        unsigned swb = sWP_b + (u & 1) * (64 * WPS * 2);
#pragma unroll
        for (int ks = 0; ks < 4; ks++){
            unsigned aF[4];
            LDSM4(aF, sA_b + 2 * ((m0g + (l & 15)) * SA_S
                                  + kc * 64 + ks * 16 + (l >> 4) * 8));
#pragma unroll
            for (int nt = 0; nt < 2; nt++){
                unsigned bfr[4];
                LDSM4T(bfr, swb + 2 * ((ks * 16 + (l & 15)) * WPS
                                        + n0p + nt * 16 + (l >> 4) * 8));
                MMA16816(acc[nt * 2],     aF, bfr[0], bfr[1]);
                MMA16816(acc[nt * 2 + 1], aF, bfr[2], bfr[3]);
            }
        }
        if (kc == 3){
            // panel complete: fold into jp, reset acc
#pragma unroll
            for (int a = 0; a < 4; a++){
                int c = np * 64 + n0p + a * 8 + 2 * (l & 3);
                float ba0 = sBA[c], ba1 = sBA[c + 1];
                float u0 = sU[c],  u1 = sU[c + 1];
                jp[0] += fmaxf(acc[a][0] + ba0, 0.f) * u0
                       + fmaxf(acc[a][1] + ba1, 0.f) * u1;
                jp[1] += fmaxf(acc[a][2] + ba0, 0.f) * u0
                       + fmaxf(acc[a][3] + ba1, 0.f) * u1;
#pragma unroll
                for (int c2 = 0; c2 < 4; c2++) acc[a][c2] = 0.f;
            }
        }
    }
    // reduce jp across quad lanes, accumulate into jsm
#pragma unroll
    for (int hh = 0; hh < 2; hh++){
        float v = jp[hh];
        v += __shfl_xor_sync(0xffffffffu, v, 1);
        v += __shfl_xor_sync(0xffffffffu, v, 2);
        if ((l & 3) == 0)
            atomicAdd(&jsm[m0g + hh * 8 + (l >> 2)], v);
    }
    __syncthreads();

    if (t < 128){
        float mv = (input_uf[row0 + t] != UNUM) ? 1.f : 0.f;
        jsm[t] = mv * expf(jsm[t]);
    }
    __syncthreads();
    if (t < 2){
        float s = 0.f;
#pragma unroll 8
        for (int q = 0; q < 64; q++) s += jsm[t * 64 + q];
        sjv[t] = 1.f / (s + 1e-8f);
    }
    __syncthreads();

    // ---- final epilogue: 512 threads = 2 b x 256 d ----
    int bb = t >> 8, d = t & 255, b = 2 * p + bb;
    float fr = 0.f;
#pragma unroll 8
    for (int ff = 0; ff < 64; ff++)
        fr += jsm[bb * 64 + ff] * __bfloat162float(sA[(bb * 64 + ff) * SA_S + d]);
    fr *= sjv[bb];
    float uidv = g_uid[b * D_ + d];
    float user = uidv + fr;
    float p0 = uidv * E[2 * d]     + user * E[2 * (256 + d)];
    float p1 = uidv * E[2 * d + 1] + user * E[2 * (256 + d) + 1];
    p0 = wred32(p0); p1 = wred32(p1);
    if (l == 0){ r0s[w] = p0; r1s[w] = p1; }
    __syncthreads();
    if (t < 2){
        float L0 = 0.f, L1 = 0.f;
#pragma unroll
        for (int q = 0; q < 8; q++){ L0 += r0s[t * 8 + q]; L1 += r1s[t * 8 + q]; }
        float mx = fmaxf(L0, L1);
        float e0 = expf(L0 - mx), e1 = expf(L1 - mx);
        float inv = 1.f / (e0 + e1);
        a0s[t] = e0 * inv; a1s[t] = e1 * inv;
    }
    __syncthreads();
    float ufv = uidv * a0s[bb] + user * a1s[bb];
    int ii = input_i[b];
    float sc = ufv * iidW[(size_t)ii * D_ + d];
    sc = wred32(sc);
    if (l == 0) r0s[w] = sc;
    __syncthreads();
    if (t < 2){
        float s = 0.f;
#pragma unroll
        for (int q = 0; q < 8; q++) s += r0s[t * 8 + q];
        out[2 * p + t] = s + i_bias[input_i[2 * p + t]];
    }
}

// ------------------------------------------------------------------
extern "C" void kernel_launch(void* const* d_in, const int* in_sizes, int n_in,
                              void* d_out, int out_size){
    const int*   input_u  = (const int*)  d_in[0];
    const int*   input_i  = (const int*)  d_in[1];
    const int*   input_uf = (const int*)  d_in[2];
    const float* uidW     = (const float*)d_in[3];
    const float* iidW     = (const float*)d_in[4];
    const float* i_bias   = (const float*)d_in[5];
    const float* Key      = (const float*)d_in[6];
    const float* MemW     = (const float*)d_in[7];
    const float* WA       = (const float*)d_in[8];
    const float* BA       = (const float*)d_in[9];
    const float* Uom      = (const float*)d_in[10];
    const float* E        = (const float*)d_in[11];
    float* out = (float*)d_out;

    size_t sm1 = (size_t)(256*KBS*2 + 64*CBS*2 + 64*36*4);

    cudaFuncSetAttribute(k1_att,   cudaFuncAttributeMaxDynamicSharedMemorySize, (int)sm1);
    cudaFuncSetAttribute(k2_fused, cudaFuncAttributeMaxDynamicSharedMemorySize, SMEM_K2);

    k_cvt<<<72, 256>>>(WA, MemW);
    k0_prep<<<B_, 256>>>(input_u, uidW);
    k1_att <<<dim3(B_/64, F_), 256, sm1>>>(input_uf, uidW, Key);
    k1b_inv<<<8, 256>>>();
    k2_fused<<<B_/2, 512, SMEM_K2>>>(input_uf, input_i, iidW, i_bias,
                                     BA, Uom, E, out);
}